// round 12
// baseline (speedup 1.0000x reference)
#include <cuda_runtime.h>
#include <cuda_fp16.h>
#include <stdint.h>

#define M_DIM 2048
#define N_DIM 11008
#define K_DIM 4096
#define K16   (K_DIM / 16)       // 256

#define BM 128
#define BN 256

// A in fragment-major layout: uint4 chunk per (m16, k16, lane)
__device__ uint4 g_xa[(size_t)(M_DIM / 16) * K16 * 32];

// ---------------------------------------------------------------------------
// convert: x f32 -> fragment-major fp16 chunks.
//   r = m16*16 + lane/4,  k0 = k16*16 + 4*(lane%4)
//   chunk = { h(x[r][k0..1]), h(x[r+8][k0..1]), h(x[r][k0+2..3]), h(x[r+8][k0+2..3]) }
// ---------------------------------------------------------------------------
__global__ void convert_x_kernel(const float* __restrict__ x) {
    int gid = blockIdx.x * blockDim.x + threadIdx.x;
    int lane = gid & 31;
    int k16 = (gid >> 5) & (K16 - 1);
    int m16 = gid >> 13;
    int r = m16 * 16 + (lane >> 2);
    int k0 = k16 * 16 + (lane & 3) * 4;
    float4 p = *(const float4*)(x + (size_t)r * K_DIM + k0);
    float4 q = *(const float4*)(x + (size_t)(r + 8) * K_DIM + k0);
    __half2 u0 = __floats2half2_rn(p.x, p.y);
    __half2 u1 = __floats2half2_rn(q.x, q.y);
    __half2 u2 = __floats2half2_rn(p.z, p.w);
    __half2 u3 = __floats2half2_rn(q.z, q.w);
    uint4 v;
    v.x = *(uint32_t*)&u0; v.y = *(uint32_t*)&u1;
    v.z = *(uint32_t*)&u2; v.w = *(uint32_t*)&u3;
    g_xa[gid] = v;
}

// ---------------------------------------------------------------------------
__device__ __forceinline__ void mma_16816(float c[4], const uint32_t a[4],
                                          const uint32_t b[2]) {
    asm volatile(
        "mma.sync.aligned.m16n8k16.row.col.f32.f16.f16.f32 "
        "{%0,%1,%2,%3}, {%4,%5,%6,%7}, {%8,%9}, {%0,%1,%2,%3};"
        : "+f"(c[0]), "+f"(c[1]), "+f"(c[2]), "+f"(c[3])
        : "r"(a[0]), "r"(a[1]), "r"(a[2]), "r"(a[3]), "r"(b[0]), "r"(b[1]));
}

// ---------------------------------------------------------------------------
// out[m,n] = scale[n]*sum_k x[m,k]*(W[k,n]-zero[n]) + bias[n]
// block 128x256, 8 warps (2m x 4n), warp tile 64x64.
// NO shared memory, NO barriers: A fragments via coalesced LDG.128 from the
// fragment-major g_xa; B words direct from packed qw; both prefetched
// distance-2 (k16) into the just-consumed register slots.
// ---------------------------------------------------------------------------
__global__ void __launch_bounds__(256, 1)
qgemm_kernel(const uint32_t* __restrict__ qw, const float* __restrict__ scales,
             const int* __restrict__ zeros, const float* __restrict__ bias,
             float* __restrict__ out) {
    const int tid = threadIdx.x;
    const int lane = tid & 31;
    const int wid = tid >> 5;
    const int warp_m = wid & 1;   // 0..1 -> 64-row slabs
    const int warp_n = wid >> 1;  // 0..3 -> 64-col slabs
    const int bm0 = blockIdx.x * BM;
    const int bn0 = blockIdx.y * BN;

    // A fragment base: chunk((bm0/16 + warp_m*4 + mi), kk)[lane]
    const uint4* Abase =
        g_xa + ((size_t)(bm0 / 16 + warp_m * 4) * K16) * 32 + lane;

    // B fragment base: lane owns (k4 = lane%4, n = nb)
    const int nb = bn0 + warp_n * 64 + (lane >> 2);
    const uint32_t* Bg = qw + (size_t)(lane & 3) * N_DIM + nb;

    __half2 zc[8];
#pragma unroll
    for (int nj = 0; nj < 8; nj++)
        zc[nj] = __half2half2(
            __float2half_rn(1024.0f + (float)zeros[nb + nj * 8]));

    float acc[4][8][4];
#pragma unroll
    for (int mi = 0; mi < 4; mi++)
#pragma unroll
        for (int ni = 0; ni < 8; ni++)
#pragma unroll
            for (int t = 0; t < 4; t++) acc[mi][ni][t] = 0.0f;

    uint32_t af[2][4][4];
    uint32_t br[2][8];

#define LOAD_A(SLOT, KK)                                                       \
    do {                                                                       \
        _Pragma("unroll") for (int mi = 0; mi < 4; mi++) {                     \
            uint4 v = __ldg(Abase + (size_t)mi * (K16 * 32) + (KK) * 32);      \
            af[SLOT][mi][0] = v.x; af[SLOT][mi][1] = v.y;                      \
            af[SLOT][mi][2] = v.z; af[SLOT][mi][3] = v.w;                      \
        }                                                                      \
    } while (0)

    // ---- prologue: slots hold k16 = 0, 1 ----
    LOAD_A(0, 0);
    LOAD_A(1, 1);
#pragma unroll
    for (int g = 0; g < 2; g++)
#pragma unroll
        for (int nj = 0; nj < 8; nj++)
            br[g][nj] = Bg[(size_t)(g * 4) * N_DIM + nj * 8];

#pragma unroll 2
    for (int kk = 0; kk < K16; kk++) {
        const int cur = kk & 1;
        const int kn = (kk + 2) & (K16 - 1);  // wraps at tail: harmless reload

        // B: dequant current slot, refill with k16 = kk+2
#pragma unroll
        for (int nj = 0; nj < 8; nj++) {
            uint32_t w = br[cur][nj];
            uint32_t lo = __byte_perm(w, 0x64646464u, 0x4140);
            uint32_t hi = __byte_perm(w, 0x64646464u, 0x4342);
            __half2 h0 = __hsub2(*(__half2*)&lo, zc[nj]);
            __half2 h1 = __hsub2(*(__half2*)&hi, zc[nj]);
            uint32_t bf[2];
            bf[0] = *(uint32_t*)&h0;
            bf[1] = *(uint32_t*)&h1;
            br[cur][nj] = Bg[(size_t)(kn * 4) * N_DIM + nj * 8];
#pragma unroll
            for (int mi = 0; mi < 4; mi++)
                mma_16816(acc[mi][nj], af[cur][mi], bf);
        }
        // A: refill consumed slot with k16 = kk+2 (distance-2 cover)
        LOAD_A(cur, kn);
    }

    // ---- epilogue ----
    const int m0 = bm0 + warp_m * 64;
    const int n0w = bn0 + warp_n * 64;
    const int elr = lane >> 2;
    const int elc = (lane & 3) * 2;
#pragma unroll
    for (int ni = 0; ni < 8; ni++) {
        const int col = n0w + ni * 8 + elc;
        const float s0 = scales[col], s1 = scales[col + 1];
        const float b0 = bias[col], b1 = bias[col + 1];
#pragma unroll
        for (int mi = 0; mi < 4; mi++) {
            const int r0 = m0 + mi * 16 + elr;
            float2 v0 = make_float2(acc[mi][ni][0] * s0 + b0,
                                    acc[mi][ni][1] * s1 + b1);
            *(float2*)(out + (size_t)r0 * N_DIM + col) = v0;
            float2 v1 = make_float2(acc[mi][ni][2] * s0 + b0,
                                    acc[mi][ni][3] * s1 + b1);
            *(float2*)(out + (size_t)(r0 + 8) * N_DIM + col) = v1;
        }
    }
}

// ---------------------------------------------------------------------------
extern "C" void kernel_launch(void* const* d_in, const int* in_sizes, int n_in,
                              void* d_out, int out_size) {
    const float* x = (const float*)d_in[0];
    const uint32_t* qw = (const uint32_t*)d_in[1];
    const float* scales = (const float*)d_in[2];
    const int* zeros = (const int*)d_in[3];
    const float* bias = (const float*)d_in[4];
    float* out = (float*)d_out;

    convert_x_kernel<<<(M_DIM / 16) * K16 * 32 / 256, 256>>>(x);

    dim3 grid(M_DIM / BM, N_DIM / BN);  // 16 x 43 (m fastest: B L2 reuse)
    qgemm_kernel<<<grid, 256>>>(qw, scales, zeros, bias, out);
}

// round 13
// speedup vs baseline: 1.3702x; 1.3702x over previous
#include <cuda_runtime.h>
#include <cuda_fp16.h>
#include <stdint.h>

#define M_DIM 2048
#define N_DIM 11008
#define K_DIM 4096
#define K16   (K_DIM / 16)       // 256
#define NT32  (N_DIM / 32)       // 344 n-tiles

#define BM 128
#define BN 128

// A in fragment-major layout: uint4 chunk per (m16, k16, lane)
__device__ uint4 g_xa[(size_t)(M_DIM / 16) * K16 * 32];
// B in fragment-major layout: uint4 chunk per (ntile32, k16, lane)
__device__ uint4 g_wb[(size_t)NT32 * K16 * 32];

// ---------------------------------------------------------------------------
// convert: x f32 -> fragment-major fp16 chunks.
//   r = m16*16 + lane/4,  k0 = k16*16 + 4*(lane%4)
// ---------------------------------------------------------------------------
__global__ void convert_x_kernel(const float* __restrict__ x) {
    int gid = blockIdx.x * blockDim.x + threadIdx.x;
    int lane = gid & 31;
    int k16 = (gid >> 5) & (K16 - 1);
    int m16 = gid >> 13;
    int r = m16 * 16 + (lane >> 2);
    int k0 = k16 * 16 + (lane & 3) * 4;
    float4 p = *(const float4*)(x + (size_t)r * K_DIM + k0);
    float4 q = *(const float4*)(x + (size_t)(r + 8) * K_DIM + k0);
    __half2 u0 = __floats2half2_rn(p.x, p.y);
    __half2 u1 = __floats2half2_rn(q.x, q.y);
    __half2 u2 = __floats2half2_rn(p.z, p.w);
    __half2 u3 = __floats2half2_rn(q.z, q.w);
    uint4 v;
    v.x = *(uint32_t*)&u0; v.y = *(uint32_t*)&u1;
    v.z = *(uint32_t*)&u2; v.w = *(uint32_t*)&u3;
    g_xa[gid] = v;
}

// ---------------------------------------------------------------------------
// reorder B: chunk(bt, k16)[lane] = { qw[k16*4 + lane%4][bt*32 + lane/4 + 8*nj] }
// ---------------------------------------------------------------------------
__global__ void reorder_b_kernel(const uint32_t* __restrict__ qw) {
    int gid = blockIdx.x * blockDim.x + threadIdx.x;   // one uint4 each
    int lane = gid & 31;
    int k16 = (gid >> 5) & (K16 - 1);
    int bt = gid >> 13;                                 // 0..343
    const uint32_t* src =
        qw + (size_t)(k16 * 4 + (lane & 3)) * N_DIM + bt * 32 + (lane >> 2);
    uint4 v;
    v.x = src[0];
    v.y = src[8];
    v.z = src[16];
    v.w = src[24];
    g_wb[gid] = v;
}

// ---------------------------------------------------------------------------
__device__ __forceinline__ void mma_16816(float c[4], const uint32_t a[4],
                                          const uint32_t b[2]) {
    asm volatile(
        "mma.sync.aligned.m16n8k16.row.col.f32.f16.f16.f32 "
        "{%0,%1,%2,%3}, {%4,%5,%6,%7}, {%8,%9}, {%0,%1,%2,%3};"
        : "+f"(c[0]), "+f"(c[1]), "+f"(c[2]), "+f"(c[3])
        : "r"(a[0]), "r"(a[1]), "r"(a[2]), "r"(a[3]), "r"(b[0]), "r"(b[1]));
}

// ---------------------------------------------------------------------------
// out[m,n] = scale[n]*sum_k x[m,k]*(W[k,n]-zero[n]) + bias[n]
// block 128x128, 8 warps (2m x 4n), warp tile 64x32, 2 CTAs/SM.
// NO smem, NO barriers. A: 4 x LDG.128 per k16 (fragment-major g_xa).
// B: 1 x LDG.128 per k16 (fragment-major g_wb). Distance-2 prefetch.
// ---------------------------------------------------------------------------
__global__ void __launch_bounds__(256, 2)
qgemm_kernel(const float* __restrict__ scales, const int* __restrict__ zeros,
             const float* __restrict__ bias, float* __restrict__ out) {
    const int tid = threadIdx.x;
    const int lane = tid & 31;
    const int wid = tid >> 5;
    const int warp_m = wid & 1;   // 0..1 -> 64-row slabs
    const int warp_n = wid >> 1;  // 0..3 -> 32-col slabs
    const int bm0 = blockIdx.x * BM;
    const int bn0 = blockIdx.y * BN;

    // A fragment base: chunk((bm0/16 + warp_m*4 + mi), kk)[lane]
    const uint4* Abase =
        g_xa + ((size_t)(bm0 / 16 + warp_m * 4) * K16) * 32 + lane;
    // B fragment base: chunk(bt, kk)[lane]
    const uint4* Bbase =
        g_wb + ((size_t)(bn0 / 32 + warp_n) * K16) * 32 + lane;

    const int nb = bn0 + warp_n * 32 + (lane >> 2);
    __half2 zc[4];
#pragma unroll
    for (int nj = 0; nj < 4; nj++)
        zc[nj] = __half2half2(
            __float2half_rn(1024.0f + (float)zeros[nb + nj * 8]));

    float acc[4][4][4];
#pragma unroll
    for (int mi = 0; mi < 4; mi++)
#pragma unroll
        for (int ni = 0; ni < 4; ni++)
#pragma unroll
            for (int t = 0; t < 4; t++) acc[mi][ni][t] = 0.0f;

    uint32_t af[2][4][4];
    uint4 br[2];

#define LOAD_A(SLOT, KK)                                                       \
    do {                                                                       \
        _Pragma("unroll") for (int mi = 0; mi < 4; mi++) {                     \
            uint4 v = __ldg(Abase + (size_t)mi * (K16 * 32) + (KK) * 32);      \
            af[SLOT][mi][0] = v.x; af[SLOT][mi][1] = v.y;                      \
            af[SLOT][mi][2] = v.z; af[SLOT][mi][3] = v.w;                      \
        }                                                                      \
    } while (0)

    // ---- prologue: slots hold k16 = 0, 1 ----
    LOAD_A(0, 0);
    LOAD_A(1, 1);
    br[0] = __ldg(Bbase);
    br[1] = __ldg(Bbase + 32);

#pragma unroll 4
    for (int kk = 0; kk < K16; kk++) {
        const int cur = kk & 1;
        const int kn = (kk + 2) & (K16 - 1);  // wraps at tail: harmless reload

        const uint32_t* bw = (const uint32_t*)&br[cur];
        uint32_t w0 = bw[0], w1 = bw[1], w2 = bw[2], w3 = bw[3];
        // refill B slot early (distance-2 cover)
        br[cur] = __ldg(Bbase + (size_t)kn * 32);

#pragma unroll
        for (int nj = 0; nj < 4; nj++) {
            uint32_t w = (nj == 0) ? w0 : (nj == 1) ? w1 : (nj == 2) ? w2 : w3;
            uint32_t lo = __byte_perm(w, 0x64646464u, 0x4140);
            uint32_t hi = __byte_perm(w, 0x64646464u, 0x4342);
            __half2 h0 = __hsub2(*(__half2*)&lo, zc[nj]);
            __half2 h1 = __hsub2(*(__half2*)&hi, zc[nj]);
            uint32_t bf[2];
            bf[0] = *(uint32_t*)&h0;
            bf[1] = *(uint32_t*)&h1;
#pragma unroll
            for (int mi = 0; mi < 4; mi++)
                mma_16816(acc[mi][nj], af[cur][mi], bf);
        }
        // A: refill consumed slot with k16 = kk+2
        LOAD_A(cur, kn);
    }

    // ---- epilogue ----
    const int m0 = bm0 + warp_m * 64;
    const int n0w = bn0 + warp_n * 32;
    const int elr = lane >> 2;
    const int elc = (lane & 3) * 2;
#pragma unroll
    for (int ni = 0; ni < 4; ni++) {
        const int col = n0w + ni * 8 + elc;
        const float s0 = scales[col], s1 = scales[col + 1];
        const float b0 = bias[col], b1 = bias[col + 1];
#pragma unroll
        for (int mi = 0; mi < 4; mi++) {
            const int r0 = m0 + mi * 16 + elr;
            float2 v0 = make_float2(acc[mi][ni][0] * s0 + b0,
                                    acc[mi][ni][1] * s1 + b1);
            *(float2*)(out + (size_t)r0 * N_DIM + col) = v0;
            float2 v1 = make_float2(acc[mi][ni][2] * s0 + b0,
                                    acc[mi][ni][3] * s1 + b1);
            *(float2*)(out + (size_t)(r0 + 8) * N_DIM + col) = v1;
        }
    }
}

// ---------------------------------------------------------------------------
extern "C" void kernel_launch(void* const* d_in, const int* in_sizes, int n_in,
                              void* d_out, int out_size) {
    const float* x = (const float*)d_in[0];
    const uint32_t* qw = (const uint32_t*)d_in[1];
    const float* scales = (const float*)d_in[2];
    const int* zeros = (const int*)d_in[3];
    const float* bias = (const float*)d_in[4];
    float* out = (float*)d_out;

    convert_x_kernel<<<(M_DIM / 16) * K16 * 32 / 256, 256>>>(x);
    reorder_b_kernel<<<NT32 * K16 * 32 / 256, 256>>>(qw);

    dim3 grid(M_DIM / BM, N_DIM / BN);  // 16 x 86 (m fastest: B L2 reuse)
    qgemm_kernel<<<grid, 256>>>(scales, zeros, bias, out);
}